// round 16
// baseline (speedup 1.0000x reference)
#include <cuda_runtime.h>
#include <cstdint>

#define B_   2
#define A_   512
#define T_   512
#define F_   128
#define RBF_ 25
#define TBLK 64
#define NBLK (T_/TBLK)

// Precomputed y = x @ Win, [B,A,F]
__device__ __align__(16) float g_y[B_ * A_ * F_];

// ---------------- smem layout (float offsets) ----------------
#define OFF_WF1T 0        // [128][36] tf32 (g-major)    4608
#define OFF_BF1  4608     // 128
#define OFF_RS   4736     // 2 x [64][36] raw f32        4608 (buf stride 2304)
#define OFF_NJ   9344     // 2 x 64 int
#define OFF_NK   9472     // 2 x 64 int
#define OFF_MSK  9600     // 2 x 64 f32
#define OFF_GS   9728     // 128
#define OFF_PRT  9856     // 2*128
#define OFF_ACC  10112    // 128
#define OFF_H1T  10240    // [128][68] tf32 (g-major)    8704  } contiguous 17408
#define OFF_GT   18944    // [128][68] tf32 (f-major)    8704  }  -> Wf2 overlay
#define SMEM_FLOATS 27648
#define SMEM_BYTES  (SMEM_FLOATS * 4)   // 110592 B -> 2 CTAs/SM

#define BUFR 2304

#define LN2 0.69314718055994530942f

static __device__ __forceinline__ float ssp(float v) {
    float e = __expf(-fabsf(v));
    return fmaxf(v, 0.0f) + LN2 * __log2f(1.0f + e) - LN2;
}
static __device__ __forceinline__ uint32_t f2t(float f) {
    uint32_t r;
    asm("cvt.rna.tf32.f32 %0, %1;" : "=r"(r) : "f"(f));
    return r;
}
static __device__ __forceinline__ void mma8(float* d, const uint32_t* a,
                                            uint32_t b0, uint32_t b1) {
    asm volatile(
        "mma.sync.aligned.m16n8k8.row.col.f32.tf32.tf32.f32 "
        "{%0,%1,%2,%3}, {%4,%5,%6,%7}, {%8,%9}, {%0,%1,%2,%3};"
        : "+f"(d[0]), "+f"(d[1]), "+f"(d[2]), "+f"(d[3])
        : "r"(a[0]), "r"(a[1]), "r"(a[2]), "r"(a[3]),
          "r"(b0), "r"(b1));
}
#define LDSM_X4(r, addr) \
    asm volatile("ldmatrix.sync.aligned.m8n8.x4.shared.b16 {%0,%1,%2,%3}, [%4];" \
        : "=r"((r)[0]), "=r"((r)[1]), "=r"((r)[2]), "=r"((r)[3]) : "r"(addr))

static __device__ __forceinline__ uint32_t smem_u32(const void* p) {
    uint32_t a;
    asm("{ .reg .u64 t; cvta.to.shared.u64 t, %1; cvt.u32.u64 %0, t; }"
        : "=r"(a) : "l"(p));
    return a;
}
#define CP_ASYNC4(dst, src) \
    asm volatile("cp.async.ca.shared.global [%0], [%1], 4;" \
                 :: "r"(dst), "l"(src) : "memory")
#define CP_COMMIT() asm volatile("cp.async.commit_group;" ::: "memory")
#define CP_WAIT0()  asm volatile("cp.async.wait_group 0;" ::: "memory")

// ---------------------------------------------------------------------------
// Kernel 1: y[ba,f] = sum_i x[ba,i] * Win[i,f]  (4 atoms/CTA)
// ---------------------------------------------------------------------------
__global__ __launch_bounds__(128) void y_kernel(const float* __restrict__ x,
                                                const float* __restrict__ Win) {
    const int ba0 = blockIdx.x * 4;
    const int f   = threadIdx.x;
    __shared__ float xs[4][F_];
#pragma unroll
    for (int a = 0; a < 4; a++)
        xs[a][f] = x[(ba0 + a) * F_ + f];
    __syncthreads();
    float acc0 = 0.f, acc1 = 0.f, acc2 = 0.f, acc3 = 0.f;
#pragma unroll 16
    for (int i = 0; i < F_; i++) {
        float w = Win[i * F_ + f];
        acc0 = fmaf(xs[0][i], w, acc0);
        acc1 = fmaf(xs[1][i], w, acc1);
        acc2 = fmaf(xs[2][i], w, acc2);
        acc3 = fmaf(xs[3][i], w, acc3);
    }
    g_y[(ba0 + 0) * F_ + f] = acc0;
    g_y[(ba0 + 1) * F_ + f] = acc1;
    g_y[(ba0 + 2) * F_ + f] = acc2;
    g_y[(ba0 + 3) * F_ + f] = acc3;
}

// ---------------------------------------------------------------------------
// Prefetch one 64-triplet block into buffer par via cp.async. 256 threads.
// ---------------------------------------------------------------------------
static __device__ __forceinline__ void issue_prefetch(
    uint32_t sb, int tid, uint32_t t0g, int par,
    const float* __restrict__ r_ij,
    const int* __restrict__ nbr_j, const int* __restrict__ nbr_k,
    const float* __restrict__ mask)
{
    const uint32_t rsb = sb + (uint32_t)(OFF_RS + par * BUFR) * 4u;
#pragma unroll
    for (int j = 0; j < 8; j++) {
        uint32_t idx = (uint32_t)tid + j * 256;
        uint32_t t = idx >> 5, r = idx & 31;
        if (r < RBF_)
            CP_ASYNC4(rsb + (t * 36 + r) * 4, r_ij + (size_t)(t0g + t) * RBF_ + r);
    }
    if (tid < 64)
        CP_ASYNC4(sb + (OFF_NJ + par * 64 + tid) * 4, nbr_j + t0g + tid);
    else if (tid < 128)
        CP_ASYNC4(sb + (OFF_NK + par * 64 + (tid - 64)) * 4, nbr_k + t0g + (tid - 64));
    else if (tid < 192)
        CP_ASYNC4(sb + (OFF_MSK + par * 64 + (tid - 128)) * 4, mask + t0g + (tid - 128));
    CP_COMMIT();
}

// ---------------------------------------------------------------------------
// Fused kernel. One 256-thread CTA per (b,a); 2 CTAs/SM. ldmatrix operand feed.
// ---------------------------------------------------------------------------
__global__ __launch_bounds__(256, 2) void cfconv_mma(
    const float* __restrict__ r_ij,
    const float* __restrict__ mask,
    const float* __restrict__ Wf1,
    const float* __restrict__ bf1,
    const float* __restrict__ Wf2,
    const float* __restrict__ bf2,
    const float* __restrict__ Wout,
    const float* __restrict__ bout,
    const int*   __restrict__ nbr_j,
    const int*   __restrict__ nbr_k,
    float*       __restrict__ out)
{
    extern __shared__ float sm[];
    uint32_t* smu = (uint32_t*)sm;
    const uint32_t sb = smem_u32(sm);

    const int tid  = threadIdx.x;
    const int wid  = tid >> 5;
    const int lane = tid & 31;
    const int gr   = lane >> 2;
    const int t4   = lane & 3;
    const int ba   = blockIdx.x;
    const int b    = ba / A_;

    // ldmatrix lane-address components
    const uint32_t la = lane & 7;
    const uint32_t lb = (lane >> 3) & 1;
    const uint32_t lc = lane >> 4;
    const uint32_t rowA = la + 8 * lb;   // A-frag: bit3 -> row+8, bit4 -> col+4
    const uint32_t colA = 4 * lc;
    const uint32_t rowB = la + 8 * lc;   // B-frag: bit4 -> row+8, bit3 -> col+4
    const uint32_t colB = 4 * lb;

    // zero RS pad cols [25,32) for both buffers (never rewritten)
    for (int i = tid; i < 2 * TBLK * 7; i += 256) {
        int buf = i / (TBLK * 7);
        int k = i - buf * (TBLK * 7);
        int t = k / 7, r = 25 + (k - t * 7);
        sm[OFF_RS + buf * BUFR + t * 36 + r] = 0.0f;
    }
    issue_prefetch(sb, tid, (uint32_t)ba * T_, 0, r_ij, nbr_j, nbr_k, mask);

    // one-time weights: Wf1T[g][k] (g-major, K padded 25->32)
    for (int i = tid; i < F_ * 32; i += 256) {
        int g = i >> 5, k = i & 31;
        float v = (k < RBF_) ? Wf1[k * F_ + g] : 0.0f;
        smu[OFF_WF1T + g * 36 + k] = f2t(v);
    }
    if (tid < 128) sm[OFF_BF1 + tid] = bf1[tid];

    // stage-2 tile per warp: f-rows [wm*32,+32), g-cols [wn*64,+64)
    const int wm = wid & 3, wn = wid >> 2;
    const int m0 = wm * 32, n0 = wn * 64;
    float P[2][8][4];
#pragma unroll
    for (int mt = 0; mt < 2; mt++)
#pragma unroll
        for (int nt = 0; nt < 8; nt++)
#pragma unroll
            for (int j = 0; j < 4; j++) P[mt][nt][j] = 0.0f;

    // stage-2 ldmatrix base addresses (bytes)
    const uint32_t adrA0 = sb + (OFF_GT  + (m0 + rowA) * 68 + colA) * 4;
    const uint32_t adrA1 = adrA0 + 16 * 68 * 4;
    const uint32_t adrB  = sb + (OFF_H1T + (n0 + rowB) * 68 + colB) * 4;

    float gsum0 = 0.0f, gsum1 = 0.0f;

    CP_WAIT0();
    __syncthreads();

    for (int blk = 0; blk < NBLK; blk++) {
        const int par = blk & 1;

        if (tid < 128) {
            // ===== stage 1: H1T[g][t] = ssp(R @ Wf1 + bf1), 16 t-rows/warp =====
            const int tb = wid * 16;
            const uint32_t adrRS = sb + (OFF_RS + par * BUFR
                                         + (tb + rowA) * 36 + colA) * 4;
            const uint32_t adrW  = sb + (OFF_WF1T + rowB * 36 + colB) * 4;
            // H1T write base: c = nb + nt*8 + 2*t4, row = tb+gr
            const uint32_t hw = OFF_H1T + (2 * t4) * 68 + tb + gr;
#pragma unroll
            for (int half = 0; half < 2; half++) {
                const int nb = half * 64;
                float s1[8][4];
#pragma unroll
                for (int nt = 0; nt < 8; nt++)
#pragma unroll
                    for (int j = 0; j < 4; j++) s1[nt][j] = 0.0f;

#pragma unroll
                for (int k = 0; k < 4; k++) {
                    uint32_t a[4];
                    LDSM_X4(a, adrRS + k * 32);
#pragma unroll
                    for (int p = 0; p < 4; p++) {
                        uint32_t bq[4];
                        LDSM_X4(bq, adrW + (nb + p * 16) * 36 * 4 + k * 32);
                        mma8(s1[2 * p],     a, bq[0], bq[1]);
                        mma8(s1[2 * p + 1], a, bq[2], bq[3]);
                    }
                }
#pragma unroll
                for (int nt = 0; nt < 8; nt++) {
                    int c = nb + nt * 8 + 2 * t4;
                    float bc0 = sm[OFF_BF1 + c];
                    float bc1 = sm[OFF_BF1 + c + 1];
                    uint32_t w0 = hw + (uint32_t)(nb + nt * 8) * 68;
                    smu[w0]           = f2t(ssp(s1[nt][0] + bc0));
                    smu[w0 + 68]      = f2t(ssp(s1[nt][1] + bc1));
                    smu[w0 + 8]       = f2t(ssp(s1[nt][2] + bc0));
                    smu[w0 + 68 + 8]  = f2t(ssp(s1[nt][3] + bc1));
                }
            }
        } else {
            // ===== gather: thread per f, all 64 t's, batched LDG =====
            const uint32_t f = tid - 128;
            const float* yb  = g_y + (uint32_t)b * (A_ * F_) + f;
            const int*   sNj = (const int*)(sm + OFF_NJ + par * 64);
            const int*   sNk = (const int*)(sm + OFF_NK + par * 64);
            const float* sM  = sm + OFF_MSK + par * 64;
#pragma unroll
            for (int tt = 0; tt < TBLK; tt += 8) {
                float vj[8], vk[8];
#pragma unroll
                for (int w = 0; w < 8; w++) {
                    vj[w] = yb[(uint32_t)sNj[tt + w] * F_];
                    vk[w] = yb[(uint32_t)sNk[tt + w] * F_];
                }
                uint4 q0, q1;
                uint32_t* g0 = (uint32_t*)&q0;
                uint32_t* g1 = (uint32_t*)&q1;
#pragma unroll
                for (int w = 0; w < 8; w++) {
                    float gv = vj[w] * vk[w] * sM[tt + w];
                    if (w < 4) { gsum0 += gv; g0[w] = f2t(gv); }
                    else       { gsum1 += gv; g1[w - 4] = f2t(gv); }
                }
                *(uint4*)&smu[OFF_GT + f * 68 + tt]     = q0;
                *(uint4*)&smu[OFF_GT + f * 68 + tt + 4] = q1;
            }
        }
        __syncthreads();

        if (blk + 1 < NBLK)
            issue_prefetch(sb, tid, (uint32_t)ba * T_ + (blk + 1) * TBLK,
                           par ^ 1, r_ij, nbr_j, nbr_k, mask);

        // ===== stage 2: P += G^T @ H1 (K=64), ldmatrix operand feed =====
#pragma unroll
        for (int k = 0; k < 8; k++) {
            uint32_t a0q[4], a1q[4];
            LDSM_X4(a0q, adrA0 + k * 32);
            LDSM_X4(a1q, adrA1 + k * 32);
#pragma unroll
            for (int p = 0; p < 4; p++) {
                uint32_t bq[4];
                LDSM_X4(bq, adrB + p * 16 * 68 * 4 + k * 32);
                mma8(P[0][2 * p],     a0q, bq[0], bq[1]);
                mma8(P[1][2 * p],     a1q, bq[0], bq[1]);
                mma8(P[0][2 * p + 1], a0q, bq[2], bq[3]);
                mma8(P[1][2 * p + 1], a1q, bq[2], bq[3]);
            }
        }
        CP_WAIT0();
        __syncthreads();
    }

    // ---- epilogue ----
    if (tid >= 128) sm[OFF_GS + (tid - 128)] = gsum0 + gsum1;
    __syncthreads();
    // Wf2[g][f] overlay into contiguous H1T..GT region (17408 >= 16384)
    for (int i = tid; i < F_ * F_; i += 256) sm[OFF_H1T + i] = Wf2[i];
    __syncthreads();

#pragma unroll
    for (int mt = 0; mt < 2; mt++) {
        int f0 = m0 + mt * 16 + gr;
        int f1 = f0 + 8;
        float p0 = 0.0f, p1 = 0.0f;
#pragma unroll
        for (int nt = 0; nt < 8; nt++) {
            int c = n0 + nt * 8 + 2 * t4;
            p0 += P[mt][nt][0] * sm[OFF_H1T + c * F_ + f0]
                + P[mt][nt][1] * sm[OFF_H1T + (c + 1) * F_ + f0];
            p1 += P[mt][nt][2] * sm[OFF_H1T + c * F_ + f1]
                + P[mt][nt][3] * sm[OFF_H1T + (c + 1) * F_ + f1];
        }
        p0 += __shfl_xor_sync(0xFFFFFFFFu, p0, 1);
        p0 += __shfl_xor_sync(0xFFFFFFFFu, p0, 2);
        p1 += __shfl_xor_sync(0xFFFFFFFFu, p1, 1);
        p1 += __shfl_xor_sync(0xFFFFFFFFu, p1, 2);
        if (t4 == 0) {
            sm[OFF_PRT + wn * F_ + f0] = p0;
            sm[OFF_PRT + wn * F_ + f1] = p1;
        }
    }
    __syncthreads();

    if (tid < 128) {
        float acc = sm[OFF_PRT + tid] + sm[OFF_PRT + F_ + tid]
                  + bf2[tid] * sm[OFF_GS + tid];
        sm[OFF_ACC + tid] = acc;
    }
    __syncthreads();

    if (tid < 128) {
        float o = bout[tid];
#pragma unroll 8
        for (int g = 0; g < F_; g++)
            o = fmaf(sm[OFF_ACC + g], Wout[g * F_ + tid], o);
        out[(uint32_t)ba * F_ + tid] = ssp(o);
    }
}

// ---------------------------------------------------------------------------
extern "C" void kernel_launch(void* const* d_in, const int* in_sizes, int n_in,
                              void* d_out, int out_size)
{
    const float* x     = (const float*)d_in[0];
    const float* r_ij  = (const float*)d_in[1];
    const float* mask  = (const float*)d_in[2];
    const float* Wf1   = (const float*)d_in[3];
    const float* bf1   = (const float*)d_in[4];
    const float* Wf2   = (const float*)d_in[5];
    const float* bf2   = (const float*)d_in[6];
    const float* Win   = (const float*)d_in[7];
    const float* Wout  = (const float*)d_in[8];
    const float* bout  = (const float*)d_in[9];
    const int*   nbr_j = (const int*)d_in[10];
    const int*   nbr_k = (const int*)d_in[11];
    float* out = (float*)d_out;

    cudaFuncSetAttribute(cfconv_mma,
                         cudaFuncAttributeMaxDynamicSharedMemorySize,
                         SMEM_BYTES);

    y_kernel<<<B_ * A_ / 4, 128>>>(x, Win);
    cfconv_mma<<<B_ * A_, 256, SMEM_BYTES>>>(
        r_ij, mask, Wf1, bf1, Wf2, bf2, Wout, bout, nbr_j, nbr_k, out);
}